// round 4
// baseline (speedup 1.0000x reference)
#include <cuda_runtime.h>
#include <cuda_bf16.h>
#include <math.h>
#include <stdint.h>

// ---------------------------------------------------------------------------
// GraphAE on GB300 (sm_103 plain target -> mma.sync tensor path).
// pseudo == 0 => only spline weight k=0 contributes.
// All activations carried as bf16 hi/lo plane pairs (fp32-accurate when
// recombined; feeds 3-product error-compensated bf16 MMA directly).
//   CSR build -> agg1(gather x) -> G1 -> h(planes)
//   G2: h @ [W2|root2] -> hWr(planes) -> agg2 -> z(planes)
//   G3: z@dec_w1 relu -> h2(planes) ; G4: h2@dec_w2 -> out(fp32)
// GEMM: B (hi/lo) resident in smem; A chunks cp.async double-buffered.
// ---------------------------------------------------------------------------

#define NNODES 50000
#define NEDGES 800000
#define NB_SCAN 49

// ------------------------- scratch (static device) -------------------------
__device__ int   g_cnt[NNODES];
__device__ int   g_rowptr[NNODES + 1];
__device__ int   g_cursor[NNODES];
__device__ int   g_csr[NEDGES];
__device__ float g_invdeg[NNODES];
__device__ int   g_scantmp[NNODES];
__device__ int   g_bsum[NB_SCAN];
__device__ int   g_boff[NB_SCAN];

// activation planes (bf16 hi/lo)
__device__ __nv_bfloat16 g_A1h[(size_t)NNODES * 128], g_A1l[(size_t)NNODES * 128];
__device__ __nv_bfloat16 g_hh[(size_t)NNODES * 256],  g_hl[(size_t)NNODES * 256];
__device__ __nv_bfloat16 g_wh[(size_t)NNODES * 128],  g_wl[(size_t)NNODES * 128]; // hWr
__device__ __nv_bfloat16 g_zh[(size_t)NNODES * 64],   g_zl[(size_t)NNODES * 64];
__device__ __nv_bfloat16 g_2h[(size_t)NNODES * 256],  g_2l[(size_t)NNODES * 256]; // h2

// bf16 hi/lo split weights, natural [k][n] row-major
__device__ __nv_bfloat16 g_B1h[128 * 256], g_B1l[128 * 256];
__device__ __nv_bfloat16 g_B2h[256 * 128], g_B2l[256 * 128];
__device__ __nv_bfloat16 g_D1h[64 * 256],  g_D1l[64 * 256];
__device__ __nv_bfloat16 g_D2h[256 * 64],  g_D2l[256 * 64];
__device__ float g_b2c[128];                   // [0 | conv2_b]

// ------------------------------ helpers ------------------------------------
__device__ __forceinline__ uint32_t smem_u32(const void* p) {
    uint32_t a;
    asm("{ .reg .u64 t; cvta.to.shared.u64 t, %1; cvt.u32.u64 %0, t; }"
        : "=r"(a) : "l"(p));
    return a;
}
__device__ __forceinline__ void ldsm_x4(uint32_t* r, uint32_t addr) {
    asm volatile("ldmatrix.sync.aligned.m8n8.x4.shared.b16 {%0,%1,%2,%3}, [%4];"
                 : "=r"(r[0]), "=r"(r[1]), "=r"(r[2]), "=r"(r[3]) : "r"(addr));
}
__device__ __forceinline__ void ldsm_x4t(uint32_t* r, uint32_t addr) {
    asm volatile("ldmatrix.sync.aligned.m8n8.x4.trans.shared.b16 {%0,%1,%2,%3}, [%4];"
                 : "=r"(r[0]), "=r"(r[1]), "=r"(r[2]), "=r"(r[3]) : "r"(addr));
}
__device__ __forceinline__ void mma_bf16(float* d, const uint32_t* a,
                                         uint32_t b0, uint32_t b1) {
    asm volatile("mma.sync.aligned.m16n8k16.row.col.f32.bf16.bf16.f32 "
                 "{%0,%1,%2,%3}, {%4,%5,%6,%7}, {%8,%9}, {%0,%1,%2,%3};"
                 : "+f"(d[0]), "+f"(d[1]), "+f"(d[2]), "+f"(d[3])
                 : "r"(a[0]), "r"(a[1]), "r"(a[2]), "r"(a[3]), "r"(b0), "r"(b1));
}
__device__ __forceinline__ void cpa16(uint32_t dst, const void* src, int srcsize) {
    asm volatile("cp.async.cg.shared.global [%0], [%1], 16, %2;"
                 :: "r"(dst), "l"(src), "r"(srcsize));
}
#define CP_COMMIT() asm volatile("cp.async.commit_group;" ::: "memory")
#define CP_WAIT0()  asm volatile("cp.async.wait_group 0;" ::: "memory")
#define CP_WAIT1()  asm volatile("cp.async.wait_group 1;" ::: "memory")

__device__ __forceinline__ void split1(float v, uint16_t& h, uint16_t& l) {
    __nv_bfloat16 hb = __float2bfloat16_rn(v);
    float r = v - __bfloat162float(hb);
    __nv_bfloat16 lb = __float2bfloat16_rn(r);
    h = __bfloat16_as_ushort(hb);
    l = __bfloat16_as_ushort(lb);
}
__device__ __forceinline__ void split_pair(float a, float b, uint32_t& hp, uint32_t& lp) {
    uint16_t h0, l0, h1, l1;
    split1(a, h0, l0); split1(b, h1, l1);
    hp = (uint32_t)h0 | ((uint32_t)h1 << 16);
    lp = (uint32_t)l0 | ((uint32_t)l1 << 16);
}
__device__ __forceinline__ float2 bf2f(uint32_t u) {
    __nv_bfloat162 t = *reinterpret_cast<__nv_bfloat162*>(&u);
    return __bfloat1622float2(t);
}

// ------------------------------ weight prep --------------------------------
__global__ void prep_k(const float* __restrict__ c1W, const float* __restrict__ c1r,
                       const float* __restrict__ c2W, const float* __restrict__ c2r,
                       const float* __restrict__ c2b,
                       const float* __restrict__ dw1, const float* __restrict__ dw2) {
    int i = blockIdx.x * blockDim.x + threadIdx.x;
    uint16_t h, l;
    if (i < 128 * 256) {  // B1 [k=128][n=256]
        int k = i >> 8, n = i & 255;
        float v = (k < 64) ? c1W[k * 256 + n] : c1r[(k - 64) * 256 + n];
        split1(v, h, l);
        g_B1h[i] = __ushort_as_bfloat16(h); g_B1l[i] = __ushort_as_bfloat16(l);
    }
    if (i < 256 * 128) {  // B2 [k=256][n=128]
        int k = i >> 7, n = i & 127;
        float v = (n < 64) ? c2W[k * 64 + n] : c2r[k * 64 + (n - 64)];
        split1(v, h, l);
        g_B2h[i] = __ushort_as_bfloat16(h); g_B2l[i] = __ushort_as_bfloat16(l);
    }
    if (i < 64 * 256) {   // D1 [k=64][n=256]
        split1(dw1[i], h, l);
        g_D1h[i] = __ushort_as_bfloat16(h); g_D1l[i] = __ushort_as_bfloat16(l);
    }
    if (i < 256 * 64) {   // D2 [k=256][n=64]
        split1(dw2[i], h, l);
        g_D2h[i] = __ushort_as_bfloat16(h); g_D2l[i] = __ushort_as_bfloat16(l);
    }
    if (i < 128) g_b2c[i] = (i < 64) ? 0.0f : c2b[i - 64];
}

// ------------------------------- CSR build ---------------------------------
__global__ void hist_k(const int* __restrict__ ei) {
    int e = blockIdx.x * blockDim.x + threadIdx.x;
    if (e < NEDGES) atomicAdd(&g_cnt[ei[NEDGES + e]], 1);
}

__global__ void scan1_k() {
    __shared__ int sh[1024];
    int i = blockIdx.x * 1024 + threadIdx.x;
    int v = (i < NNODES) ? g_cnt[i] : 0;
    sh[threadIdx.x] = v;
    __syncthreads();
    #pragma unroll
    for (int off = 1; off < 1024; off <<= 1) {
        int t = (threadIdx.x >= off) ? sh[threadIdx.x - off] : 0;
        __syncthreads();
        sh[threadIdx.x] += t;
        __syncthreads();
    }
    if (i < NNODES) g_scantmp[i] = sh[threadIdx.x];
    if (threadIdx.x == 1023) g_bsum[blockIdx.x] = sh[1023];
}

__global__ void scan2_k() {
    __shared__ int sh[64];
    int i = threadIdx.x;
    int v = (i < NB_SCAN) ? g_bsum[i] : 0;
    sh[i] = v;
    __syncthreads();
    #pragma unroll
    for (int off = 1; off < 64; off <<= 1) {
        int t = (i >= off) ? sh[i - off] : 0;
        __syncthreads();
        sh[i] += t;
        __syncthreads();
    }
    if (i < NB_SCAN) g_boff[i] = sh[i] - v;
}

__global__ void scan3_k() {
    int i = blockIdx.x * blockDim.x + threadIdx.x;
    if (i < NNODES) {
        int incl = g_scantmp[i] + g_boff[i >> 10];
        int c = g_cnt[i];
        int start = incl - c;
        g_rowptr[i] = start;
        g_cursor[i] = start;
        g_invdeg[i] = 1.0f / fmaxf((float)c, 1.0f);
        if (i == NNODES - 1) g_rowptr[NNODES] = incl;
    }
}

__global__ void place_k(const int* __restrict__ ei) {
    int e = blockIdx.x * blockDim.x + threadIdx.x;
    if (e < NEDGES) {
        int d = ei[NEDGES + e];
        int p = atomicAdd(&g_cursor[d], 1);
        g_csr[p] = ei[e];  // src
    }
}

// --------------------------- gather aggregations ---------------------------
// warp per node; lane owns feature pair (2*lane, 2*lane+1)
__global__ void agg1_k(const float* __restrict__ x) {
    int gt = blockIdx.x * blockDim.x + threadIdx.x;
    int node = gt >> 5;
    if (node >= NNODES) return;
    int lane = gt & 31;
    int beg = g_rowptr[node], end = g_rowptr[node + 1];
    float s0 = 0.f, s1 = 0.f;
    for (int i = beg; i < end; i++) {
        int s = g_csr[i];
        float2 v = __ldg((const float2*)(x + (size_t)s * 64 + 2 * lane));
        s0 += v.x; s1 += v.y;
    }
    float iv = g_invdeg[node];
    float2 xv = __ldg((const float2*)(x + (size_t)node * 64 + 2 * lane));
    uint32_t hp, lp;
    size_t o = (size_t)node * 128 + 2 * lane;
    split_pair(s0 * iv, s1 * iv, hp, lp);
    *(uint32_t*)(g_A1h + o) = hp; *(uint32_t*)(g_A1l + o) = lp;
    split_pair(xv.x, xv.y, hp, lp);
    *(uint32_t*)(g_A1h + o + 64) = hp; *(uint32_t*)(g_A1l + o + 64) = lp;
}

// z = gather(hW)*invdeg + hroot (hW = cols 0:64 of hWr planes, hroot 64:128)
__global__ void agg2_k() {
    int gt = blockIdx.x * blockDim.x + threadIdx.x;
    int node = gt >> 5;
    if (node >= NNODES) return;
    int lane = gt & 31;
    int beg = g_rowptr[node], end = g_rowptr[node + 1];
    float s0 = 0.f, s1 = 0.f;
    for (int i = beg; i < end; i++) {
        int s = g_csr[i];
        size_t o = (size_t)s * 128 + 2 * lane;
        float2 h = bf2f(__ldg((const uint32_t*)(g_wh + o)));
        float2 l = bf2f(__ldg((const uint32_t*)(g_wl + o)));
        s0 += h.x + l.x; s1 += h.y + l.y;
    }
    float iv = g_invdeg[node];
    size_t ro = (size_t)node * 128 + 64 + 2 * lane;
    float2 rh = bf2f(*(const uint32_t*)(g_wh + ro));
    float2 rl = bf2f(*(const uint32_t*)(g_wl + ro));
    float z0 = s0 * iv + rh.x + rl.x;
    float z1 = s1 * iv + rh.y + rl.y;
    uint32_t hp, lp;
    split_pair(z0, z1, hp, lp);
    size_t zo = (size_t)node * 64 + 2 * lane;
    *(uint32_t*)(g_zh + zo) = hp; *(uint32_t*)(g_zl + zo) = lp;
}

// ------------------------ bf16 mma.sync GEMM -------------------------------
// C[128, NC] per CTA. 8 warps 4(m)x2(n); warp = 32 rows x NC/2 cols.
// B (hi/lo) fully resident in smem; A chunks (KC=32) cp.async double-buffered.
// acc += Ah*Bh + Ah*Bl + Al*Bh (fp32 accum).
template <int K, int NC, bool RELU, bool SPLITOUT>
__global__ void __launch_bounds__(256, 1)
mgemm_k(const __nv_bfloat16* __restrict__ Ah, const __nv_bfloat16* __restrict__ Al,
        const __nv_bfloat16* __restrict__ Bh, const __nv_bfloat16* __restrict__ Bl,
        const float* __restrict__ bias,
        float* __restrict__ Cf, __nv_bfloat16* __restrict__ Ch,
        __nv_bfloat16* __restrict__ Cl, int nRows) {
    constexpr int KC = 32;
    constexpr int NCH = K / KC;
    constexpr int SB = NC + 8;            // B smem row stride (elems)
    constexpr int SBB = K * SB * 2;       // bytes per B plane
    constexpr int APL = 128 * 40 * 2;     // A plane bytes per buffer (stride 40 elems)
    constexpr int ABUF = 2 * APL;
    constexpr int OA0 = 2 * SBB;
    constexpr int NT  = NC / 16;
    constexpr int NTG = NC / 32;

    extern __shared__ char dsm[];
    uint32_t sbase = smem_u32(dsm);

    const int tid = threadIdx.x;
    const int wid = tid >> 5, lane = tid & 31;
    const int wm = wid & 3, wn = wid >> 2;
    const int col0 = wn * (NC / 2);
    const int n0 = blockIdx.x * 128;
    int rem = nRows - n0;
    if (rem > 128) rem = 128;

    const int lrow = lane & 15, lhalf = lane >> 4;

    // ---- stage resident B (both planes) ----
    {
        constexpr int G8 = NC / 8;
        for (int idx = tid; idx < K * G8; idx += 256) {
            int row = idx / G8, g = idx - row * G8;
            uint32_t dst = sbase + (uint32_t)(row * (SB * 2) + g * 16);
            cpa16(dst, (const char*)(Bh + (size_t)row * NC) + g * 16, 16);
            cpa16(dst + SBB, (const char*)(Bl + (size_t)row * NC) + g * 16, 16);
        }
    }
    // ---- stage A chunk 0 into buffer 0 ----
    {
        #pragma unroll
        for (int it = 0; it < 2; it++) {
            int idx = it * 256 + tid;
            int row = idx >> 2, j = idx & 3;
            int ss = (row < rem) ? 16 : 0;
            uint32_t dst = sbase + OA0 + (uint32_t)(row * 80 + j * 16);
            const char* sh = (const char*)(Ah + (size_t)(n0 + row) * K) + j * 16;
            const char* sl = (const char*)(Al + (size_t)(n0 + row) * K) + j * 16;
            cpa16(dst, sh, ss);
            cpa16(dst + APL, sl, ss);
        }
    }
    CP_COMMIT();

    float acc[2][NT][4];
    #pragma unroll
    for (int mt = 0; mt < 2; mt++)
        #pragma unroll
        for (int j = 0; j < NT; j++)
            #pragma unroll
            for (int q = 0; q < 4; q++) acc[mt][j][q] = 0.f;

    for (int c = 0; c < NCH; c++) {
        if (c + 1 < NCH) {
            const int c0n = (c + 1) * KC;
            uint32_t ob = sbase + OA0 + (uint32_t)(((c + 1) & 1) * ABUF);
            #pragma unroll
            for (int it = 0; it < 2; it++) {
                int idx = it * 256 + tid;
                int row = idx >> 2, j = idx & 3;
                int ss = (row < rem) ? 16 : 0;
                uint32_t dst = ob + (uint32_t)(row * 80 + j * 16);
                const char* sh = (const char*)(Ah + (size_t)(n0 + row) * K + c0n) + j * 16;
                const char* sl = (const char*)(Al + (size_t)(n0 + row) * K + c0n) + j * 16;
                cpa16(dst, sh, ss);
                cpa16(dst + APL, sl, ss);
            }
            CP_COMMIT();
            CP_WAIT1();
        } else {
            CP_WAIT0();
        }
        __syncthreads();

        const int c0 = c * KC;
        uint32_t ab = sbase + OA0 + (uint32_t)((c & 1) * ABUF);
        #pragma unroll
        for (int kk = 0; kk < KC; kk += 16) {
            uint32_t ah[2][4], al[2][4];
            #pragma unroll
            for (int mt = 0; mt < 2; mt++) {
                uint32_t ra = ab +
                    (uint32_t)((32 * wm + 16 * mt + lrow) * 80 + kk * 2 + lhalf * 16);
                ldsm_x4(ah[mt], ra);
                ldsm_x4(al[mt], ra + APL);
            }
            #pragma unroll
            for (int ng = 0; ng < NTG; ng++) {
                uint32_t rb = sbase +
                    (uint32_t)(((c0 + kk + lrow) * SB + col0 + ng * 16) * 2 + lhalf * 16);
                uint32_t bh[4], bl[4];
                ldsm_x4t(bh, rb);
                ldsm_x4t(bl, rb + SBB);
                #pragma unroll
                for (int mt = 0; mt < 2; mt++) {
                    mma_bf16(acc[mt][2 * ng],     ah[mt], bh[0], bh[1]);
                    mma_bf16(acc[mt][2 * ng],     ah[mt], bl[0], bl[1]);
                    mma_bf16(acc[mt][2 * ng],     al[mt], bh[0], bh[1]);
                    mma_bf16(acc[mt][2 * ng + 1], ah[mt], bh[2], bh[3]);
                    mma_bf16(acc[mt][2 * ng + 1], ah[mt], bl[2], bl[3]);
                    mma_bf16(acc[mt][2 * ng + 1], al[mt], bh[2], bh[3]);
                }
            }
        }
        __syncthreads();
    }

    // ---- epilogue ----
    const int qr = lane >> 2;          // 0..7
    const int qc = (lane & 3) << 1;    // 0,2,4,6
    #pragma unroll
    for (int mt = 0; mt < 2; mt++) {
        int row0 = 32 * wm + 16 * mt + qr;
        int row1 = row0 + 8;
        #pragma unroll
        for (int j = 0; j < NT; j++) {
            int col = col0 + 8 * j + qc;
            float b0 = __ldg(&bias[col]), b1 = __ldg(&bias[col + 1]);
            float v00 = acc[mt][j][0] + b0, v01 = acc[mt][j][1] + b1;
            float v10 = acc[mt][j][2] + b0, v11 = acc[mt][j][3] + b1;
            if (RELU) {
                v00 = fmaxf(v00, 0.f); v01 = fmaxf(v01, 0.f);
                v10 = fmaxf(v10, 0.f); v11 = fmaxf(v11, 0.f);
            }
            if (SPLITOUT) {
                uint32_t hp, lp;
                if (row0 < rem) {
                    size_t o = (size_t)(n0 + row0) * NC + col;
                    split_pair(v00, v01, hp, lp);
                    *(uint32_t*)(Ch + o) = hp; *(uint32_t*)(Cl + o) = lp;
                }
                if (row1 < rem) {
                    size_t o = (size_t)(n0 + row1) * NC + col;
                    split_pair(v10, v11, hp, lp);
                    *(uint32_t*)(Ch + o) = hp; *(uint32_t*)(Cl + o) = lp;
                }
            } else {
                if (row0 < rem)
                    *(float2*)(Cf + (size_t)(n0 + row0) * NC + col) = make_float2(v00, v01);
                if (row1 < rem)
                    *(float2*)(Cf + (size_t)(n0 + row1) * NC + col) = make_float2(v10, v11);
            }
        }
    }
}

// ------------------------------- launcher ----------------------------------
extern "C" void kernel_launch(void* const* d_in, const int* in_sizes, int n_in,
                              void* d_out, int out_size) {
    const float* x   = (const float*)d_in[0];
    const int*   ei  = (const int*)d_in[1];
    const float* c1W = (const float*)d_in[2];
    const float* c1r = (const float*)d_in[3];
    const float* c1b = (const float*)d_in[4];
    const float* c2W = (const float*)d_in[5];
    const float* c2r = (const float*)d_in[6];
    const float* c2b = (const float*)d_in[7];
    const float* dw1 = (const float*)d_in[8];
    const float* db1 = (const float*)d_in[9];
    const float* dw2 = (const float*)d_in[10];
    const float* db2 = (const float*)d_in[11];
    float* out = (float*)d_out;

    void *pCnt, *pB2c;
    void *pA1h, *pA1l, *pHh, *pHl, *pWh, *pWl, *pZh, *pZl, *p2h, *p2l;
    void *pB1h, *pB1l, *pB2h, *pB2l, *pD1h, *pD1l, *pD2h, *pD2l;
    cudaGetSymbolAddress(&pCnt, g_cnt);
    cudaGetSymbolAddress(&pB2c, g_b2c);
    cudaGetSymbolAddress(&pA1h, g_A1h); cudaGetSymbolAddress(&pA1l, g_A1l);
    cudaGetSymbolAddress(&pHh, g_hh);   cudaGetSymbolAddress(&pHl, g_hl);
    cudaGetSymbolAddress(&pWh, g_wh);   cudaGetSymbolAddress(&pWl, g_wl);
    cudaGetSymbolAddress(&pZh, g_zh);   cudaGetSymbolAddress(&pZl, g_zl);
    cudaGetSymbolAddress(&p2h, g_2h);   cudaGetSymbolAddress(&p2l, g_2l);
    cudaGetSymbolAddress(&pB1h, g_B1h); cudaGetSymbolAddress(&pB1l, g_B1l);
    cudaGetSymbolAddress(&pB2h, g_B2h); cudaGetSymbolAddress(&pB2l, g_B2l);
    cudaGetSymbolAddress(&pD1h, g_D1h); cudaGetSymbolAddress(&pD1l, g_D1l);
    cudaGetSymbolAddress(&pD2h, g_D2h); cudaGetSymbolAddress(&pD2l, g_D2l);

    // smem: 2 B planes (K*(NC+8)*2 each) + 2 A buffers (20480B each)
    const int SM_G1 = 2 * (128 * 264 * 2) + 40960;  // 176128
    const int SM_G2 = 2 * (256 * 136 * 2) + 40960;  // 180224
    const int SM_G3 = 2 * (64 * 264 * 2) + 40960;   // 108544
    const int SM_G4 = 2 * (256 * 72 * 2) + 40960;   // 114688
    cudaFuncSetAttribute(mgemm_k<128, 256, true,  true>,  cudaFuncAttributeMaxDynamicSharedMemorySize, SM_G1);
    cudaFuncSetAttribute(mgemm_k<256, 128, false, true>,  cudaFuncAttributeMaxDynamicSharedMemorySize, SM_G2);
    cudaFuncSetAttribute(mgemm_k<64, 256, true,  true>,   cudaFuncAttributeMaxDynamicSharedMemorySize, SM_G3);
    cudaFuncSetAttribute(mgemm_k<256, 64, false, false>,  cudaFuncAttributeMaxDynamicSharedMemorySize, SM_G4);

    const int nTG = (NNODES + 127) / 128;               // 391
    const int nEdgeBlocks = (NEDGES + 255) / 256;
    const int nAggBlocks  = (NNODES * 32 + 255) / 256;
    const int nNodeBlocks = (NNODES + 255) / 256;

    // --- CSR build + weight prep ---
    cudaMemsetAsync(pCnt, 0, NNODES * sizeof(int));
    prep_k<<<128, 256>>>(c1W, c1r, c2W, c2r, c2b, dw1, dw2);
    hist_k<<<nEdgeBlocks, 256>>>(ei);
    scan1_k<<<NB_SCAN, 1024>>>();
    scan2_k<<<1, 64>>>();
    scan3_k<<<nNodeBlocks, 256>>>();
    place_k<<<nEdgeBlocks, 256>>>(ei);

    // --- conv1 ---
    agg1_k<<<nAggBlocks, 256>>>(x);
    mgemm_k<128, 256, true, true><<<nTG, 256, SM_G1>>>(
        (const __nv_bfloat16*)pA1h, (const __nv_bfloat16*)pA1l,
        (const __nv_bfloat16*)pB1h, (const __nv_bfloat16*)pB1l,
        c1b, nullptr, (__nv_bfloat16*)pHh, (__nv_bfloat16*)pHl, NNODES);

    // --- conv2 (scatter h@W2 instead of h) ---
    mgemm_k<256, 128, false, true><<<nTG, 256, SM_G2>>>(
        (const __nv_bfloat16*)pHh, (const __nv_bfloat16*)pHl,
        (const __nv_bfloat16*)pB2h, (const __nv_bfloat16*)pB2l,
        (const float*)pB2c, nullptr, (__nv_bfloat16*)pWh, (__nv_bfloat16*)pWl, NNODES);
    agg2_k<<<nAggBlocks, 256>>>();

    // --- decoder ---
    mgemm_k<64, 256, true, true><<<nTG, 256, SM_G3>>>(
        (const __nv_bfloat16*)pZh, (const __nv_bfloat16*)pZl,
        (const __nv_bfloat16*)pD1h, (const __nv_bfloat16*)pD1l,
        db1, nullptr, (__nv_bfloat16*)p2h, (__nv_bfloat16*)p2l, NNODES);
    mgemm_k<256, 64, false, false><<<nTG, 256, SM_G4>>>(
        (const __nv_bfloat16*)p2h, (const __nv_bfloat16*)p2l,
        (const __nv_bfloat16*)pD2h, (const __nv_bfloat16*)pD2l,
        db2, out, nullptr, nullptr, NNODES);
}

// round 5
// speedup vs baseline: 1.0185x; 1.0185x over previous
#include <cuda_runtime.h>
#include <cuda_bf16.h>
#include <math.h>
#include <stdint.h>

// ---------------------------------------------------------------------------
// GraphAE on GB300 (sm_103 plain target -> mma.sync tensor path).
// pseudo == 0 => only spline weight k=0 contributes.
// Activations carried as bf16 hi/lo plane pairs; 3-product compensated bf16
// MMA (fp32 accum) == fp32-accurate GEMMs.
//   CSR build -> agg1(gather x) -> G1 -> h(planes)
//   G2: h @ [W2|root2] -> hWr(planes) -> agg2 -> z(planes)
//   G3: z@dec_w1 relu -> h2(planes) ; G4: h2@dec_w2 -> out(fp32)
// GEMM: single-buffered per-chunk staging (small smem -> occ 4+), cp.async.
// ---------------------------------------------------------------------------

#define NNODES 50000
#define NEDGES 800000
#define NB_SCAN 49

// ------------------------- scratch (static device) -------------------------
__device__ int   g_cnt[NNODES];
__device__ int   g_rowptr[NNODES + 1];
__device__ int   g_cursor[NNODES];
__device__ int   g_csr[NEDGES];
__device__ float g_invdeg[NNODES];
__device__ int   g_scantmp[NNODES];
__device__ int   g_bsum[NB_SCAN];

// activation planes (bf16 hi/lo)
__device__ __nv_bfloat16 g_A1h[(size_t)NNODES * 128], g_A1l[(size_t)NNODES * 128];
__device__ __nv_bfloat16 g_hh[(size_t)NNODES * 256],  g_hl[(size_t)NNODES * 256];
__device__ __nv_bfloat16 g_wh[(size_t)NNODES * 128],  g_wl[(size_t)NNODES * 128]; // hWr
__device__ __nv_bfloat16 g_zh[(size_t)NNODES * 64],   g_zl[(size_t)NNODES * 64];
__device__ __nv_bfloat16 g_2h[(size_t)NNODES * 256],  g_2l[(size_t)NNODES * 256]; // h2

// bf16 hi/lo split weights, natural [k][n] row-major
__device__ __nv_bfloat16 g_B1h[128 * 256], g_B1l[128 * 256];
__device__ __nv_bfloat16 g_B2h[256 * 128], g_B2l[256 * 128];
__device__ __nv_bfloat16 g_D1h[64 * 256],  g_D1l[64 * 256];
__device__ __nv_bfloat16 g_D2h[256 * 64],  g_D2l[256 * 64];
__device__ float g_b2c[128];                   // [0 | conv2_b]

// ------------------------------ helpers ------------------------------------
__device__ __forceinline__ uint32_t smem_u32(const void* p) {
    uint32_t a;
    asm("{ .reg .u64 t; cvta.to.shared.u64 t, %1; cvt.u32.u64 %0, t; }"
        : "=r"(a) : "l"(p));
    return a;
}
__device__ __forceinline__ void ldsm_x4(uint32_t* r, uint32_t addr) {
    asm volatile("ldmatrix.sync.aligned.m8n8.x4.shared.b16 {%0,%1,%2,%3}, [%4];"
                 : "=r"(r[0]), "=r"(r[1]), "=r"(r[2]), "=r"(r[3]) : "r"(addr));
}
__device__ __forceinline__ void ldsm_x4t(uint32_t* r, uint32_t addr) {
    asm volatile("ldmatrix.sync.aligned.m8n8.x4.trans.shared.b16 {%0,%1,%2,%3}, [%4];"
                 : "=r"(r[0]), "=r"(r[1]), "=r"(r[2]), "=r"(r[3]) : "r"(addr));
}
__device__ __forceinline__ void mma_bf16(float* d, const uint32_t* a,
                                         uint32_t b0, uint32_t b1) {
    asm volatile("mma.sync.aligned.m16n8k16.row.col.f32.bf16.bf16.f32 "
                 "{%0,%1,%2,%3}, {%4,%5,%6,%7}, {%8,%9}, {%0,%1,%2,%3};"
                 : "+f"(d[0]), "+f"(d[1]), "+f"(d[2]), "+f"(d[3])
                 : "r"(a[0]), "r"(a[1]), "r"(a[2]), "r"(a[3]), "r"(b0), "r"(b1));
}
__device__ __forceinline__ void cpa16(uint32_t dst, const void* src) {
    asm volatile("cp.async.cg.shared.global [%0], [%1], 16;"
                 :: "r"(dst), "l"(src));
}
#define CP_COMMIT() asm volatile("cp.async.commit_group;" ::: "memory")
#define CP_WAIT0()  asm volatile("cp.async.wait_group 0;" ::: "memory")

__device__ __forceinline__ void split1(float v, uint16_t& h, uint16_t& l) {
    __nv_bfloat16 hb = __float2bfloat16_rn(v);
    float r = v - __bfloat162float(hb);
    __nv_bfloat16 lb = __float2bfloat16_rn(r);
    h = __bfloat16_as_ushort(hb);
    l = __bfloat16_as_ushort(lb);
}
__device__ __forceinline__ void split_pair(float a, float b, uint32_t& hp, uint32_t& lp) {
    uint16_t h0, l0, h1, l1;
    split1(a, h0, l0); split1(b, h1, l1);
    hp = (uint32_t)h0 | ((uint32_t)h1 << 16);
    lp = (uint32_t)l0 | ((uint32_t)l1 << 16);
}
__device__ __forceinline__ float2 bf2f(uint32_t u) {
    __nv_bfloat162 t = *reinterpret_cast<__nv_bfloat162*>(&u);
    return __bfloat1622float2(t);
}

// ------------------------------ weight prep --------------------------------
__global__ void prep_k(const float* __restrict__ c1W, const float* __restrict__ c1r,
                       const float* __restrict__ c2W, const float* __restrict__ c2r,
                       const float* __restrict__ c2b,
                       const float* __restrict__ dw1, const float* __restrict__ dw2) {
    int i = blockIdx.x * blockDim.x + threadIdx.x;
    uint16_t h, l;
    if (i < 128 * 256) {  // B1 [k=128][n=256]
        int k = i >> 8, n = i & 255;
        float v = (k < 64) ? c1W[k * 256 + n] : c1r[(k - 64) * 256 + n];
        split1(v, h, l);
        g_B1h[i] = __ushort_as_bfloat16(h); g_B1l[i] = __ushort_as_bfloat16(l);
    }
    if (i < 256 * 128) {  // B2 [k=256][n=128]
        int k = i >> 7, n = i & 127;
        float v = (n < 64) ? c2W[k * 64 + n] : c2r[k * 64 + (n - 64)];
        split1(v, h, l);
        g_B2h[i] = __ushort_as_bfloat16(h); g_B2l[i] = __ushort_as_bfloat16(l);
    }
    if (i < 64 * 256) {   // D1 [k=64][n=256]
        split1(dw1[i], h, l);
        g_D1h[i] = __ushort_as_bfloat16(h); g_D1l[i] = __ushort_as_bfloat16(l);
    }
    if (i < 256 * 64) {   // D2 [k=256][n=64]
        split1(dw2[i], h, l);
        g_D2h[i] = __ushort_as_bfloat16(h); g_D2l[i] = __ushort_as_bfloat16(l);
    }
    if (i < 128) g_b2c[i] = (i < 64) ? 0.0f : c2b[i - 64];
}

// ------------------------------- CSR build ---------------------------------
__global__ void hist_k(const int* __restrict__ ei) {
    int e = blockIdx.x * blockDim.x + threadIdx.x;
    if (e < NEDGES) atomicAdd(&g_cnt[ei[NEDGES + e]], 1);
}

__global__ void scan1_k() {
    __shared__ int sh[1024];
    int i = blockIdx.x * 1024 + threadIdx.x;
    int v = (i < NNODES) ? g_cnt[i] : 0;
    sh[threadIdx.x] = v;
    __syncthreads();
    #pragma unroll
    for (int off = 1; off < 1024; off <<= 1) {
        int t = (threadIdx.x >= off) ? sh[threadIdx.x - off] : 0;
        __syncthreads();
        sh[threadIdx.x] += t;
        __syncthreads();
    }
    if (i < NNODES) g_scantmp[i] = sh[threadIdx.x];
    if (threadIdx.x == 1023) g_bsum[blockIdx.x] = sh[1023];
}

// scan3 folds the 49-block-sum prefix scan in (redundantly per block).
__global__ void scan3_k() {
    __shared__ int sb[64], so[64];
    int tid = threadIdx.x;
    if (tid < 64) {
        int v = (tid < NB_SCAN) ? g_bsum[tid] : 0;
        so[tid] = v;
        sb[tid] = v;
    }
    __syncthreads();
    #pragma unroll
    for (int off = 1; off < 64; off <<= 1) {
        int t = 0;
        if (tid < 64 && tid >= off) t = sb[tid - off];
        __syncthreads();
        if (tid < 64) sb[tid] += t;
        __syncthreads();
    }
    int i = blockIdx.x * blockDim.x + tid;
    if (i < NNODES) {
        int b = i >> 10;
        int boff = sb[b] - so[b];
        int incl = g_scantmp[i] + boff;
        int c = g_cnt[i];
        int start = incl - c;
        g_rowptr[i] = start;
        g_cursor[i] = start;
        g_invdeg[i] = 1.0f / fmaxf((float)c, 1.0f);
        if (i == NNODES - 1) g_rowptr[NNODES] = incl;
    }
}

__global__ void place_k(const int* __restrict__ ei) {
    int e = blockIdx.x * blockDim.x + threadIdx.x;
    if (e < NEDGES) {
        int d = ei[NEDGES + e];
        int p = atomicAdd(&g_cursor[d], 1);
        g_csr[p] = ei[e];  // src
    }
}

// --------------------------- gather aggregations ---------------------------
// warp per node; lane owns feature pair (2*lane, 2*lane+1)
__global__ void agg1_k(const float* __restrict__ x) {
    int gt = blockIdx.x * blockDim.x + threadIdx.x;
    int node = gt >> 5;
    if (node >= NNODES) return;
    int lane = gt & 31;
    int beg = g_rowptr[node], end = g_rowptr[node + 1];
    float s0 = 0.f, s1 = 0.f;
    for (int i = beg; i < end; i++) {
        int s = g_csr[i];
        float2 v = __ldg((const float2*)(x + (size_t)s * 64 + 2 * lane));
        s0 += v.x; s1 += v.y;
    }
    float iv = g_invdeg[node];
    float2 xv = __ldg((const float2*)(x + (size_t)node * 64 + 2 * lane));
    uint32_t hp, lp;
    size_t o = (size_t)node * 128 + 2 * lane;
    split_pair(s0 * iv, s1 * iv, hp, lp);
    *(uint32_t*)(g_A1h + o) = hp; *(uint32_t*)(g_A1l + o) = lp;
    split_pair(xv.x, xv.y, hp, lp);
    *(uint32_t*)(g_A1h + o + 64) = hp; *(uint32_t*)(g_A1l + o + 64) = lp;
}

// z = gather(hW)*invdeg + hroot (hW = cols 0:64 of hWr planes, hroot 64:128)
__global__ void agg2_k() {
    int gt = blockIdx.x * blockDim.x + threadIdx.x;
    int node = gt >> 5;
    if (node >= NNODES) return;
    int lane = gt & 31;
    int beg = g_rowptr[node], end = g_rowptr[node + 1];
    float s0 = 0.f, s1 = 0.f;
    for (int i = beg; i < end; i++) {
        int s = g_csr[i];
        size_t o = (size_t)s * 128 + 2 * lane;
        float2 h = bf2f(__ldg((const uint32_t*)(g_wh + o)));
        float2 l = bf2f(__ldg((const uint32_t*)(g_wl + o)));
        s0 += h.x + l.x; s1 += h.y + l.y;
    }
    float iv = g_invdeg[node];
    size_t ro = (size_t)node * 128 + 64 + 2 * lane;
    float2 rh = bf2f(*(const uint32_t*)(g_wh + ro));
    float2 rl = bf2f(*(const uint32_t*)(g_wl + ro));
    float z0 = s0 * iv + rh.x + rl.x;
    float z1 = s1 * iv + rh.y + rl.y;
    uint32_t hp, lp;
    split_pair(z0, z1, hp, lp);
    size_t zo = (size_t)node * 64 + 2 * lane;
    *(uint32_t*)(g_zh + zo) = hp; *(uint32_t*)(g_zl + zo) = lp;
}

// ------------------------ bf16 mma.sync GEMM -------------------------------
// C[128, NC] per CTA. 8 warps 4(m)x2(n); warp = 32 rows x NC/2 cols.
// Single-buffered per-chunk staging (KC=32) of A and B planes via cp.async.
// acc += Ah*Bh + Ah*Bl + Al*Bh (fp32 accum).
template <int K, int NC, bool RELU, bool SPLITOUT>
__global__ void __launch_bounds__(256)
mgemm_k(const __nv_bfloat16* __restrict__ Ah, const __nv_bfloat16* __restrict__ Al,
        const __nv_bfloat16* __restrict__ Bh, const __nv_bfloat16* __restrict__ Bl,
        const float* __restrict__ bias,
        float* __restrict__ Cf, __nv_bfloat16* __restrict__ Ch,
        __nv_bfloat16* __restrict__ Cl, int nRows) {
    constexpr int KC = 32;
    constexpr int NCH = K / KC;
    constexpr int SB = NC + 8;            // B smem row stride (elems)
    constexpr int APL = 128 * 40 * 2;     // A plane bytes (stride 40 elems)
    constexpr int SBB = KC * SB * 2;      // B plane bytes
    constexpr int OB  = 2 * APL;          // B planes offset
    constexpr int NT  = NC / 16;
    constexpr int NTG = NC / 32;

    extern __shared__ char dsm[];
    uint32_t sbase = smem_u32(dsm);

    const int tid = threadIdx.x;
    const int wid = tid >> 5, lane = tid & 31;
    const int wm = wid & 3, wn = wid >> 2;
    const int col0 = wn * (NC / 2);
    const int n0 = blockIdx.x * 128;
    int rem = nRows - n0;
    if (rem > 128) rem = 128;

    const int lrow = lane & 15, lhalf = lane >> 4;

    float acc[2][NT][4];
    #pragma unroll
    for (int mt = 0; mt < 2; mt++)
        #pragma unroll
        for (int j = 0; j < NT; j++)
            #pragma unroll
            for (int q = 0; q < 4; q++) acc[mt][j][q] = 0.f;

    for (int c = 0; c < NCH; c++) {
        const int c0 = c * KC;
        // ---- stage A chunk: 128 rows x 32 cols bf16, both planes ----
        {
            #pragma unroll
            for (int it = 0; it < 2; it++) {
                int idx = it * 256 + tid;       // 512 chunks per plane
                int row = idx >> 2, j = idx & 3;
                int gr = n0 + (row < rem ? row : rem - 1);
                uint32_t dst = sbase + (uint32_t)(row * 80 + j * 16);
                const char* sh = (const char*)(Ah + (size_t)gr * K + c0) + j * 16;
                const char* sl = (const char*)(Al + (size_t)gr * K + c0) + j * 16;
                cpa16(dst, sh);
                cpa16(dst + APL, sl);
            }
        }
        // ---- stage B chunk: 32 rows x NC bf16, both planes ----
        {
            constexpr int G8 = NC / 8;
            #pragma unroll
            for (int it = 0; it < (KC * G8 + 255) / 256; it++) {
                int idx = it * 256 + tid;
                if (KC * G8 % 256 == 0 || idx < KC * G8) {
                    int row = idx / G8, g = idx - row * G8;
                    uint32_t dst = sbase + OB + (uint32_t)(row * (SB * 2) + g * 16);
                    cpa16(dst, (const char*)(Bh + (size_t)(c0 + row) * NC) + g * 16);
                    cpa16(dst + SBB, (const char*)(Bl + (size_t)(c0 + row) * NC) + g * 16);
                }
            }
        }
        CP_COMMIT();
        CP_WAIT0();
        __syncthreads();

        // ---- compute ----
        #pragma unroll
        for (int kk = 0; kk < KC; kk += 16) {
            uint32_t ah[2][4], al[2][4];
            #pragma unroll
            for (int mt = 0; mt < 2; mt++) {
                uint32_t ra = sbase +
                    (uint32_t)((32 * wm + 16 * mt + lrow) * 80 + kk * 2 + lhalf * 16);
                ldsm_x4(ah[mt], ra);
                ldsm_x4(al[mt], ra + APL);
            }
            #pragma unroll
            for (int ng = 0; ng < NTG; ng++) {
                uint32_t rb = sbase + OB +
                    (uint32_t)(((kk + lrow) * SB + col0 + ng * 16) * 2 + lhalf * 16);
                uint32_t bh[4], bl[4];
                ldsm_x4t(bh, rb);
                ldsm_x4t(bl, rb + SBB);
                #pragma unroll
                for (int mt = 0; mt < 2; mt++) {
                    mma_bf16(acc[mt][2 * ng],     ah[mt], bh[0], bh[1]);
                    mma_bf16(acc[mt][2 * ng],     ah[mt], bl[0], bl[1]);
                    mma_bf16(acc[mt][2 * ng],     al[mt], bh[0], bh[1]);
                    mma_bf16(acc[mt][2 * ng + 1], ah[mt], bh[2], bh[3]);
                    mma_bf16(acc[mt][2 * ng + 1], ah[mt], bl[2], bl[3]);
                    mma_bf16(acc[mt][2 * ng + 1], al[mt], bh[2], bh[3]);
                }
            }
        }
        if (c + 1 < NCH) __syncthreads();
    }

    // ---- epilogue ----
    const int qr = lane >> 2;          // 0..7
    const int qc = (lane & 3) << 1;    // 0,2,4,6
    #pragma unroll
    for (int mt = 0; mt < 2; mt++) {
        int row0 = 32 * wm + 16 * mt + qr;
        int row1 = row0 + 8;
        #pragma unroll
        for (int j = 0; j < NT; j++) {
            int col = col0 + 8 * j + qc;
            float b0 = __ldg(&bias[col]), b1 = __ldg(&bias[col + 1]);
            float v00 = acc[mt][j][0] + b0, v01 = acc[mt][j][1] + b1;
            float v10 = acc[mt][j][2] + b0, v11 = acc[mt][j][3] + b1;
            if (RELU) {
                v00 = fmaxf(v00, 0.f); v01 = fmaxf(v01, 0.f);
                v10 = fmaxf(v10, 0.f); v11 = fmaxf(v11, 0.f);
            }
            if (SPLITOUT) {
                uint32_t hp, lp;
                if (row0 < rem) {
                    size_t o = (size_t)(n0 + row0) * NC + col;
                    split_pair(v00, v01, hp, lp);
                    *(uint32_t*)(Ch + o) = hp; *(uint32_t*)(Cl + o) = lp;
                }
                if (row1 < rem) {
                    size_t o = (size_t)(n0 + row1) * NC + col;
                    split_pair(v10, v11, hp, lp);
                    *(uint32_t*)(Ch + o) = hp; *(uint32_t*)(Cl + o) = lp;
                }
            } else {
                if (row0 < rem)
                    *(float2*)(Cf + (size_t)(n0 + row0) * NC + col) = make_float2(v00, v01);
                if (row1 < rem)
                    *(float2*)(Cf + (size_t)(n0 + row1) * NC + col) = make_float2(v10, v11);
            }
        }
    }
}

// ------------------------------- launcher ----------------------------------
extern "C" void kernel_launch(void* const* d_in, const int* in_sizes, int n_in,
                              void* d_out, int out_size) {
    const float* x   = (const float*)d_in[0];
    const int*   ei  = (const int*)d_in[1];
    const float* c1W = (const float*)d_in[2];
    const float* c1r = (const float*)d_in[3];
    const float* c1b = (const float*)d_in[4];
    const float* c2W = (const float*)d_in[5];
    const float* c2r = (const float*)d_in[6];
    const float* c2b = (const float*)d_in[7];
    const float* dw1 = (const float*)d_in[8];
    const float* db1 = (const float*)d_in[9];
    const float* dw2 = (const float*)d_in[10];
    const float* db2 = (const float*)d_in[11];
    float* out = (float*)d_out;

    void *pCnt, *pB2c;
    void *pA1h, *pA1l, *pHh, *pHl, *pWh, *pWl, *pZh, *pZl, *p2h, *p2l;
    void *pB1h, *pB1l, *pB2h, *pB2l, *pD1h, *pD1l, *pD2h, *pD2l;
    cudaGetSymbolAddress(&pCnt, g_cnt);
    cudaGetSymbolAddress(&pB2c, g_b2c);
    cudaGetSymbolAddress(&pA1h, g_A1h); cudaGetSymbolAddress(&pA1l, g_A1l);
    cudaGetSymbolAddress(&pHh, g_hh);   cudaGetSymbolAddress(&pHl, g_hl);
    cudaGetSymbolAddress(&pWh, g_wh);   cudaGetSymbolAddress(&pWl, g_wl);
    cudaGetSymbolAddress(&pZh, g_zh);   cudaGetSymbolAddress(&pZl, g_zl);
    cudaGetSymbolAddress(&p2h, g_2h);   cudaGetSymbolAddress(&p2l, g_2l);
    cudaGetSymbolAddress(&pB1h, g_B1h); cudaGetSymbolAddress(&pB1l, g_B1l);
    cudaGetSymbolAddress(&pB2h, g_B2h); cudaGetSymbolAddress(&pB2l, g_B2l);
    cudaGetSymbolAddress(&pD1h, g_D1h); cudaGetSymbolAddress(&pD1l, g_D1l);
    cudaGetSymbolAddress(&pD2h, g_D2h); cudaGetSymbolAddress(&pD2l, g_D2l);

    // smem: 2 A planes (10240B each) + 2 B chunk planes (32*(NC+8)*2 each)
    const int SM_N256 = 20480 + 2 * 32 * 264 * 2;  // 54272
    const int SM_N128 = 20480 + 2 * 32 * 136 * 2;  // 37888
    const int SM_N64  = 20480 + 2 * 32 * 72 * 2;   // 29696
    cudaFuncSetAttribute(mgemm_k<128, 256, true,  true>,  cudaFuncAttributeMaxDynamicSharedMemorySize, SM_N256);
    cudaFuncSetAttribute(mgemm_k<256, 128, false, true>,  cudaFuncAttributeMaxDynamicSharedMemorySize, SM_N128);
    cudaFuncSetAttribute(mgemm_k<64, 256, true,  true>,   cudaFuncAttributeMaxDynamicSharedMemorySize, SM_N256);
    cudaFuncSetAttribute(mgemm_k<256, 64, false, false>,  cudaFuncAttributeMaxDynamicSharedMemorySize, SM_N64);

    const int nTG = (NNODES + 127) / 128;               // 391
    const int nEdgeBlocks = (NEDGES + 255) / 256;
    const int nAggBlocks  = (NNODES * 32 + 255) / 256;
    const int nNodeBlocks = (NNODES + 255) / 256;

    // --- CSR build + weight prep ---
    cudaMemsetAsync(pCnt, 0, NNODES * sizeof(int));
    prep_k<<<128, 256>>>(c1W, c1r, c2W, c2r, c2b, dw1, dw2);
    hist_k<<<nEdgeBlocks, 256>>>(ei);
    scan1_k<<<NB_SCAN, 1024>>>();
    scan3_k<<<nNodeBlocks, 256>>>();
    place_k<<<nEdgeBlocks, 256>>>(ei);

    // --- conv1 ---
    agg1_k<<<nAggBlocks, 256>>>(x);
    mgemm_k<128, 256, true, true><<<nTG, 256, SM_N256>>>(
        (const __nv_bfloat16*)pA1h, (const __nv_bfloat16*)pA1l,
        (const __nv_bfloat16*)pB1h, (const __nv_bfloat16*)pB1l,
        c1b, nullptr, (__nv_bfloat16*)pHh, (__nv_bfloat16*)pHl, NNODES);

    // --- conv2 (scatter h@W2 instead of h) ---
    mgemm_k<256, 128, false, true><<<nTG, 256, SM_N128>>>(
        (const __nv_bfloat16*)pHh, (const __nv_bfloat16*)pHl,
        (const __nv_bfloat16*)pB2h, (const __nv_bfloat16*)pB2l,
        (const float*)pB2c, nullptr, (__nv_bfloat16*)pWh, (__nv_bfloat16*)pWl, NNODES);
    agg2_k<<<nAggBlocks, 256>>>();

    // --- decoder ---
    mgemm_k<64, 256, true, true><<<nTG, 256, SM_N256>>>(
        (const __nv_bfloat16*)pZh, (const __nv_bfloat16*)pZl,
        (const __nv_bfloat16*)pD1h, (const __nv_bfloat16*)pD1l,
        db1, nullptr, (__nv_bfloat16*)p2h, (__nv_bfloat16*)p2l, NNODES);
    mgemm_k<256, 64, false, false><<<nTG, 256, SM_N64>>>(
        (const __nv_bfloat16*)p2h, (const __nv_bfloat16*)p2l,
        (const __nv_bfloat16*)pD2h, (const __nv_bfloat16*)pD2l,
        db2, out, nullptr, nullptr, NNODES);
}

// round 6
// speedup vs baseline: 1.2738x; 1.2506x over previous
#include <cuda_runtime.h>
#include <cuda_bf16.h>
#include <math.h>
#include <stdint.h>

// ---------------------------------------------------------------------------
// GraphAE on GB300 (sm_103 plain target -> mma.sync tensor path).
// pseudo == 0 => only spline weight k=0 contributes.
// Activations carried as bf16 hi/lo plane pairs; 3-product compensated bf16
// MMA (fp32 accum) == fp32-accurate GEMMs.
// Pipeline (9 launches):
//   hist -> scan1 -> scan3(self-zeroing) -> place -> agg1 -> prep
//   -> FUSED[G1+G2] (h kept in smem) -> agg2 -> FUSED[G3+G4] (h2 in smem)
// ---------------------------------------------------------------------------

#define NNODES 50000
#define NEDGES 800000
#define NB_SCAN 49

// ------------------------- scratch (static device) -------------------------
__device__ int   g_cnt[NNODES];        // zero-init (BSS); scan3 restores zero
__device__ int   g_rowptr[NNODES + 1];
__device__ int   g_cursor[NNODES];
__device__ int   g_csr[NEDGES];
__device__ float g_invdeg[NNODES];
__device__ int   g_scantmp[NNODES];
__device__ int   g_bsum[NB_SCAN];

// activation planes (bf16 hi/lo)
__device__ __nv_bfloat16 g_A1h[(size_t)NNODES * 128], g_A1l[(size_t)NNODES * 128];
__device__ __nv_bfloat16 g_wh[(size_t)NNODES * 128],  g_wl[(size_t)NNODES * 128]; // hWr
__device__ __nv_bfloat16 g_zh[(size_t)NNODES * 64],   g_zl[(size_t)NNODES * 64];

// bf16 hi/lo split weights, natural [k][n] row-major
__device__ __nv_bfloat16 g_B1h[128 * 256], g_B1l[128 * 256];
__device__ __nv_bfloat16 g_B2h[256 * 128], g_B2l[256 * 128];
__device__ __nv_bfloat16 g_D1h[64 * 256],  g_D1l[64 * 256];
__device__ __nv_bfloat16 g_D2h[256 * 64],  g_D2l[256 * 64];
__device__ float g_b2c[128];                   // [0 | conv2_b]

// ------------------------------ helpers ------------------------------------
__device__ __forceinline__ uint32_t smem_u32(const void* p) {
    uint32_t a;
    asm("{ .reg .u64 t; cvta.to.shared.u64 t, %1; cvt.u32.u64 %0, t; }"
        : "=r"(a) : "l"(p));
    return a;
}
__device__ __forceinline__ void ldsm_x4(uint32_t* r, uint32_t addr) {
    asm volatile("ldmatrix.sync.aligned.m8n8.x4.shared.b16 {%0,%1,%2,%3}, [%4];"
                 : "=r"(r[0]), "=r"(r[1]), "=r"(r[2]), "=r"(r[3]) : "r"(addr));
}
__device__ __forceinline__ void ldsm_x4t(uint32_t* r, uint32_t addr) {
    asm volatile("ldmatrix.sync.aligned.m8n8.x4.trans.shared.b16 {%0,%1,%2,%3}, [%4];"
                 : "=r"(r[0]), "=r"(r[1]), "=r"(r[2]), "=r"(r[3]) : "r"(addr));
}
__device__ __forceinline__ void mma_bf16(float* d, const uint32_t* a,
                                         uint32_t b0, uint32_t b1) {
    asm volatile("mma.sync.aligned.m16n8k16.row.col.f32.bf16.bf16.f32 "
                 "{%0,%1,%2,%3}, {%4,%5,%6,%7}, {%8,%9}, {%0,%1,%2,%3};"
                 : "+f"(d[0]), "+f"(d[1]), "+f"(d[2]), "+f"(d[3])
                 : "r"(a[0]), "r"(a[1]), "r"(a[2]), "r"(a[3]), "r"(b0), "r"(b1));
}
__device__ __forceinline__ void cpa16(uint32_t dst, const void* src) {
    asm volatile("cp.async.cg.shared.global [%0], [%1], 16;"
                 :: "r"(dst), "l"(src));
}
#define CP_COMMIT() asm volatile("cp.async.commit_group;" ::: "memory")
#define CP_WAIT0()  asm volatile("cp.async.wait_group 0;" ::: "memory")

__device__ __forceinline__ void split1(float v, uint16_t& h, uint16_t& l) {
    __nv_bfloat16 hb = __float2bfloat16_rn(v);
    float r = v - __bfloat162float(hb);
    __nv_bfloat16 lb = __float2bfloat16_rn(r);
    h = __bfloat16_as_ushort(hb);
    l = __bfloat16_as_ushort(lb);
}
__device__ __forceinline__ void split_pair(float a, float b, uint32_t& hp, uint32_t& lp) {
    uint16_t h0, l0, h1, l1;
    split1(a, h0, l0); split1(b, h1, l1);
    hp = (uint32_t)h0 | ((uint32_t)h1 << 16);
    lp = (uint32_t)l0 | ((uint32_t)l1 << 16);
}
__device__ __forceinline__ float2 bf2f(uint32_t u) {
    __nv_bfloat162 t = *reinterpret_cast<__nv_bfloat162*>(&u);
    return __bfloat1622float2(t);
}

// ------------------------------ weight prep --------------------------------
__global__ void prep_k(const float* __restrict__ c1W, const float* __restrict__ c1r,
                       const float* __restrict__ c2W, const float* __restrict__ c2r,
                       const float* __restrict__ c2b,
                       const float* __restrict__ dw1, const float* __restrict__ dw2) {
    int i = blockIdx.x * blockDim.x + threadIdx.x;
    uint16_t h, l;
    if (i < 128 * 256) {  // B1 [k=128][n=256]
        int k = i >> 8, n = i & 255;
        float v = (k < 64) ? c1W[k * 256 + n] : c1r[(k - 64) * 256 + n];
        split1(v, h, l);
        g_B1h[i] = __ushort_as_bfloat16(h); g_B1l[i] = __ushort_as_bfloat16(l);
    }
    if (i < 256 * 128) {  // B2 [k=256][n=128]
        int k = i >> 7, n = i & 127;
        float v = (n < 64) ? c2W[k * 64 + n] : c2r[k * 64 + (n - 64)];
        split1(v, h, l);
        g_B2h[i] = __ushort_as_bfloat16(h); g_B2l[i] = __ushort_as_bfloat16(l);
    }
    if (i < 64 * 256) {   // D1 [k=64][n=256]
        split1(dw1[i], h, l);
        g_D1h[i] = __ushort_as_bfloat16(h); g_D1l[i] = __ushort_as_bfloat16(l);
    }
    if (i < 256 * 64) {   // D2 [k=256][n=64]
        split1(dw2[i], h, l);
        g_D2h[i] = __ushort_as_bfloat16(h); g_D2l[i] = __ushort_as_bfloat16(l);
    }
    if (i < 128) g_b2c[i] = (i < 64) ? 0.0f : c2b[i - 64];
}

// ------------------------------- CSR build ---------------------------------
__global__ void hist_k(const int* __restrict__ ei) {
    int e = blockIdx.x * blockDim.x + threadIdx.x;
    if (e < NEDGES) atomicAdd(&g_cnt[ei[NEDGES + e]], 1);
}

__global__ void scan1_k() {
    __shared__ int sh[1024];
    int i = blockIdx.x * 1024 + threadIdx.x;
    int v = (i < NNODES) ? g_cnt[i] : 0;
    sh[threadIdx.x] = v;
    __syncthreads();
    #pragma unroll
    for (int off = 1; off < 1024; off <<= 1) {
        int t = (threadIdx.x >= off) ? sh[threadIdx.x - off] : 0;
        __syncthreads();
        sh[threadIdx.x] += t;
        __syncthreads();
    }
    if (i < NNODES) g_scantmp[i] = sh[threadIdx.x];
    if (threadIdx.x == 1023) g_bsum[blockIdx.x] = sh[1023];
}

// folds the 49-block-sum scan in (redundant per block); re-zeroes g_cnt so
// the next graph replay starts from a clean histogram (no memset launch).
__global__ void scan3_k() {
    __shared__ int sb[64], so[64];
    int tid = threadIdx.x;
    if (tid < 64) {
        int v = (tid < NB_SCAN) ? g_bsum[tid] : 0;
        so[tid] = v;
        sb[tid] = v;
    }
    __syncthreads();
    #pragma unroll
    for (int off = 1; off < 64; off <<= 1) {
        int t = 0;
        if (tid < 64 && tid >= off) t = sb[tid - off];
        __syncthreads();
        if (tid < 64) sb[tid] += t;
        __syncthreads();
    }
    int i = blockIdx.x * blockDim.x + tid;
    if (i < NNODES) {
        int b = i >> 10;
        int boff = sb[b] - so[b];
        int incl = g_scantmp[i] + boff;
        int c = g_cnt[i];
        int start = incl - c;
        g_rowptr[i] = start;
        g_cursor[i] = start;
        g_invdeg[i] = 1.0f / fmaxf((float)c, 1.0f);
        g_cnt[i] = 0;                       // restore for next launch
        if (i == NNODES - 1) g_rowptr[NNODES] = incl;
    }
}

__global__ void place_k(const int* __restrict__ ei) {
    int e = blockIdx.x * blockDim.x + threadIdx.x;
    if (e < NEDGES) {
        int d = ei[NEDGES + e];
        int p = atomicAdd(&g_cursor[d], 1);
        g_csr[p] = ei[e];  // src
    }
}

// --------------------------- gather aggregations ---------------------------
// warp per node; lane owns feature pair (2*lane, 2*lane+1)
__global__ void agg1_k(const float* __restrict__ x) {
    int gt = blockIdx.x * blockDim.x + threadIdx.x;
    int node = gt >> 5;
    if (node >= NNODES) return;
    int lane = gt & 31;
    int beg = g_rowptr[node], end = g_rowptr[node + 1];
    float s0 = 0.f, s1 = 0.f;
    for (int i = beg; i < end; i++) {
        int s = g_csr[i];
        float2 v = __ldg((const float2*)(x + (size_t)s * 64 + 2 * lane));
        s0 += v.x; s1 += v.y;
    }
    float iv = g_invdeg[node];
    float2 xv = __ldg((const float2*)(x + (size_t)node * 64 + 2 * lane));
    uint32_t hp, lp;
    size_t o = (size_t)node * 128 + 2 * lane;
    split_pair(s0 * iv, s1 * iv, hp, lp);
    *(uint32_t*)(g_A1h + o) = hp; *(uint32_t*)(g_A1l + o) = lp;
    split_pair(xv.x, xv.y, hp, lp);
    *(uint32_t*)(g_A1h + o + 64) = hp; *(uint32_t*)(g_A1l + o + 64) = lp;
}

// z = gather(hW)*invdeg + hroot (hW = cols 0:64 of hWr planes, hroot 64:128)
__global__ void agg2_k() {
    int gt = blockIdx.x * blockDim.x + threadIdx.x;
    int node = gt >> 5;
    if (node >= NNODES) return;
    int lane = gt & 31;
    int beg = g_rowptr[node], end = g_rowptr[node + 1];
    float s0 = 0.f, s1 = 0.f;
    for (int i = beg; i < end; i++) {
        int s = g_csr[i];
        size_t o = (size_t)s * 128 + 2 * lane;
        float2 h = bf2f(__ldg((const uint32_t*)(g_wh + o)));
        float2 l = bf2f(__ldg((const uint32_t*)(g_wl + o)));
        s0 += h.x + l.x; s1 += h.y + l.y;
    }
    float iv = g_invdeg[node];
    size_t ro = (size_t)node * 128 + 64 + 2 * lane;
    float2 rh = bf2f(*(const uint32_t*)(g_wh + ro));
    float2 rl = bf2f(*(const uint32_t*)(g_wl + ro));
    float z0 = s0 * iv + rh.x + rl.x;
    float z1 = s1 * iv + rh.y + rl.y;
    uint32_t hp, lp;
    split_pair(z0, z1, hp, lp);
    size_t zo = (size_t)node * 64 + 2 * lane;
    *(uint32_t*)(g_zh + zo) = hp; *(uint32_t*)(g_zl + zo) = lp;
}

// -------------------- fused two-GEMM kernel (64-row tile) ------------------
// Phase1: T = relu(A[64,K1] @ B1[K1,N1=256] + bias1) -> split -> smem planes
// Phase2: out = T @ B2[K2=N1,N2] + bias2 (SPLITOUT2: bf16 planes, else fp32)
// 8 warps as 2(m) x 4(n); warp tile = 32 rows x N/4 cols. 3-product MMA.
template <int K1, int N1, int K2, int N2, bool SPLITOUT2>
__global__ void __launch_bounds__(256, 2)
fused2_k(const __nv_bfloat16* __restrict__ Ah, const __nv_bfloat16* __restrict__ Al,
         const __nv_bfloat16* __restrict__ B1h, const __nv_bfloat16* __restrict__ B1l,
         const float* __restrict__ bias1,
         const __nv_bfloat16* __restrict__ B2h, const __nv_bfloat16* __restrict__ B2l,
         const float* __restrict__ bias2,
         float* __restrict__ Cf, __nv_bfloat16* __restrict__ Ch,
         __nv_bfloat16* __restrict__ Cl, int nRows) {
    static_assert(N1 == 256 && K2 == N1, "layout assumes N1=256");
    constexpr int KC = 32;
    constexpr int NCH1 = K1 / KC, NCH2 = K2 / KC;
    constexpr int WC1 = N1 / 4, NT1 = WC1 / 8, NTG1 = WC1 / 16;
    constexpr int WC2 = N2 / 4, NT2 = WC2 / 8, NTG2 = WC2 / 16;
    constexpr int SB1 = N1 + 8, SB2 = N2 + 8;
    constexpr int HST = 264;                       // h smem row stride (elems)
    constexpr int HPL = 64 * HST * 2;              // 33792 bytes per h plane
    constexpr int OA  = 2 * HPL;                   // 67584: A stage
    constexpr int APL = 64 * 40 * 2;               // 5120 per A plane
    constexpr int OBB = OA + 2 * APL;              // 77824: B stage
    constexpr int SBB1 = KC * SB1 * 2;             // B plane bytes phase1
    constexpr int SBB2 = KC * SB2 * 2;             // phase2

    extern __shared__ char dsm[];
    uint32_t sbase = smem_u32(dsm);

    const int tid = threadIdx.x;
    const int wid = tid >> 5, lane = tid & 31;
    const int wm = wid & 1, wn = wid >> 1;
    const int n0 = blockIdx.x * 64;
    int rem = nRows - n0;
    if (rem > 64) rem = 64;

    const int lrow = lane & 15, lhalf = lane >> 4;
    const int qr = lane >> 2, qc = (lane & 3) << 1;

    // =========================== phase 1 ===========================
    {
        const int col0 = wn * WC1;
        float acc[2][NT1][4];
        #pragma unroll
        for (int mt = 0; mt < 2; mt++)
            #pragma unroll
            for (int j = 0; j < NT1; j++)
                #pragma unroll
                for (int q = 0; q < 4; q++) acc[mt][j][q] = 0.f;

        for (int c = 0; c < NCH1; c++) {
            const int c0 = c * KC;
            // stage A chunk: 64 rows x 32 cols, both planes (256 x 16B each)
            {
                int row = tid >> 2, j = tid & 3;
                int gr = n0 + (row < rem ? row : rem - 1);
                uint32_t dst = sbase + OA + (uint32_t)(row * 80 + j * 16);
                cpa16(dst, (const char*)(Ah + (size_t)gr * K1 + c0) + j * 16);
                cpa16(dst + APL, (const char*)(Al + (size_t)gr * K1 + c0) + j * 16);
            }
            // stage B1 chunk: 32 rows x N1, both planes
            {
                constexpr int G8 = N1 / 8;
                #pragma unroll
                for (int it = 0; it < KC * G8 / 256; it++) {
                    int idx = it * 256 + tid;
                    int row = idx / G8, g = idx - row * G8;
                    uint32_t dst = sbase + OBB + (uint32_t)(row * (SB1 * 2) + g * 16);
                    cpa16(dst, (const char*)(B1h + (size_t)(c0 + row) * N1) + g * 16);
                    cpa16(dst + SBB1, (const char*)(B1l + (size_t)(c0 + row) * N1) + g * 16);
                }
            }
            CP_COMMIT();
            CP_WAIT0();
            __syncthreads();

            #pragma unroll
            for (int kk = 0; kk < KC; kk += 16) {
                uint32_t ah[2][4], al[2][4];
                #pragma unroll
                for (int mt = 0; mt < 2; mt++) {
                    uint32_t ra = sbase + OA +
                        (uint32_t)((32 * wm + 16 * mt + lrow) * 80 + kk * 2 + lhalf * 16);
                    ldsm_x4(ah[mt], ra);
                    ldsm_x4(al[mt], ra + APL);
                }
                #pragma unroll
                for (int ng = 0; ng < NTG1; ng++) {
                    uint32_t rb = sbase + OBB +
                        (uint32_t)(((kk + lrow) * SB1 + col0 + ng * 16) * 2 + lhalf * 16);
                    uint32_t bh[4], bl[4];
                    ldsm_x4t(bh, rb);
                    ldsm_x4t(bl, rb + SBB1);
                    #pragma unroll
                    for (int mt = 0; mt < 2; mt++) {
                        mma_bf16(acc[mt][2 * ng],     ah[mt], bh[0], bh[1]);
                        mma_bf16(acc[mt][2 * ng],     ah[mt], bl[0], bl[1]);
                        mma_bf16(acc[mt][2 * ng],     al[mt], bh[0], bh[1]);
                        mma_bf16(acc[mt][2 * ng + 1], ah[mt], bh[2], bh[3]);
                        mma_bf16(acc[mt][2 * ng + 1], ah[mt], bl[2], bl[3]);
                        mma_bf16(acc[mt][2 * ng + 1], al[mt], bh[2], bh[3]);
                    }
                }
            }
            __syncthreads();   // before next chunk restages (or phase2 stages)
        }

        // epilogue -> h smem planes (relu + split)
        #pragma unroll
        for (int mt = 0; mt < 2; mt++) {
            int row0 = 32 * wm + 16 * mt + qr;
            #pragma unroll
            for (int j = 0; j < NT1; j++) {
                int col = col0 + 8 * j + qc;
                float b0 = __ldg(&bias1[col]), b1 = __ldg(&bias1[col + 1]);
                float v00 = fmaxf(acc[mt][j][0] + b0, 0.f);
                float v01 = fmaxf(acc[mt][j][1] + b1, 0.f);
                float v10 = fmaxf(acc[mt][j][2] + b0, 0.f);
                float v11 = fmaxf(acc[mt][j][3] + b1, 0.f);
                uint32_t hp, lp;
                uint32_t o0 = (uint32_t)((row0 * HST + col) * 2);
                split_pair(v00, v01, hp, lp);
                *(uint32_t*)(dsm + o0) = hp;
                *(uint32_t*)(dsm + HPL + o0) = lp;
                uint32_t o1 = o0 + (uint32_t)(8 * HST * 2);
                split_pair(v10, v11, hp, lp);
                *(uint32_t*)(dsm + o1) = hp;
                *(uint32_t*)(dsm + HPL + o1) = lp;
            }
        }
    }
    __syncthreads();

    // =========================== phase 2 ===========================
    {
        const int col0 = wn * WC2;
        float acc[2][NT2][4];
        #pragma unroll
        for (int mt = 0; mt < 2; mt++)
            #pragma unroll
            for (int j = 0; j < NT2; j++)
                #pragma unroll
                for (int q = 0; q < 4; q++) acc[mt][j][q] = 0.f;

        for (int c = 0; c < NCH2; c++) {
            const int c0 = c * KC;
            // stage B2 chunk
            {
                constexpr int G8 = N2 / 8;
                #pragma unroll
                for (int it = 0; it < (KC * G8 + 255) / 256; it++) {
                    int idx = it * 256 + tid;
                    if (KC * G8 % 256 == 0 || idx < KC * G8) {
                        int row = idx / G8, g = idx - row * G8;
                        uint32_t dst = sbase + OBB + (uint32_t)(row * (SB2 * 2) + g * 16);
                        cpa16(dst, (const char*)(B2h + (size_t)(c0 + row) * N2) + g * 16);
                        cpa16(dst + SBB2, (const char*)(B2l + (size_t)(c0 + row) * N2) + g * 16);
                    }
                }
            }
            CP_COMMIT();
            CP_WAIT0();
            __syncthreads();

            #pragma unroll
            for (int kk = 0; kk < KC; kk += 16) {
                uint32_t ah[2][4], al[2][4];
                #pragma unroll
                for (int mt = 0; mt < 2; mt++) {
                    uint32_t ra = sbase +
                        (uint32_t)(((32 * wm + 16 * mt + lrow) * HST + c0 + kk) * 2 + lhalf * 16);
                    ldsm_x4(ah[mt], ra);
                    ldsm_x4(al[mt], ra + HPL);
                }
                #pragma unroll
                for (int ng = 0; ng < NTG2; ng++) {
                    uint32_t rb = sbase + OBB +
                        (uint32_t)(((kk + lrow) * SB2 + col0 + ng * 16) * 2 + lhalf * 16);
                    uint32_t bh[4], bl[4];
                    ldsm_x4t(bh, rb);
                    ldsm_x4t(bl, rb + SBB2);
                    #pragma unroll
                    for (int mt = 0; mt < 2; mt++) {
                        mma_bf16(acc[mt][2 * ng],     ah[mt], bh[0], bh[1]);
                        mma_bf16(acc[mt][2 * ng],     ah[mt], bl[0], bl[1]);
                        mma_bf16(acc[mt][2 * ng],     al[mt], bh[0], bh[1]);
                        mma_bf16(acc[mt][2 * ng + 1], ah[mt], bh[2], bh[3]);
                        mma_bf16(acc[mt][2 * ng + 1], ah[mt], bl[2], bl[3]);
                        mma_bf16(acc[mt][2 * ng + 1], al[mt], bh[2], bh[3]);
                    }
                }
            }
            if (c + 1 < NCH2) __syncthreads();
        }

        // epilogue -> global
        #pragma unroll
        for (int mt = 0; mt < 2; mt++) {
            int row0 = 32 * wm + 16 * mt + qr;
            int row1 = row0 + 8;
            #pragma unroll
            for (int j = 0; j < NT2; j++) {
                int col = col0 + 8 * j + qc;
                float b0 = __ldg(&bias2[col]), b1 = __ldg(&bias2[col + 1]);
                float v00 = acc[mt][j][0] + b0, v01 = acc[mt][j][1] + b1;
                float v10 = acc[mt][j][2] + b0, v11 = acc[mt][j][3] + b1;
                if (SPLITOUT2) {
                    uint32_t hp, lp;
                    if (row0 < rem) {
                        size_t o = (size_t)(n0 + row0) * N2 + col;
                        split_pair(v00, v01, hp, lp);
                        *(uint32_t*)(Ch + o) = hp; *(uint32_t*)(Cl + o) = lp;
                    }
                    if (row1 < rem) {
                        size_t o = (size_t)(n0 + row1) * N2 + col;
                        split_pair(v10, v11, hp, lp);
                        *(uint32_t*)(Ch + o) = hp; *(uint32_t*)(Cl + o) = lp;
                    }
                } else {
                    if (row0 < rem)
                        *(float2*)(Cf + (size_t)(n0 + row0) * N2 + col) = make_float2(v00, v01);
                    if (row1 < rem)
                        *(float2*)(Cf + (size_t)(n0 + row1) * N2 + col) = make_float2(v10, v11);
                }
            }
        }
    }
}

// ------------------------------- launcher ----------------------------------
extern "C" void kernel_launch(void* const* d_in, const int* in_sizes, int n_in,
                              void* d_out, int out_size) {
    const float* x   = (const float*)d_in[0];
    const int*   ei  = (const int*)d_in[1];
    const float* c1W = (const float*)d_in[2];
    const float* c1r = (const float*)d_in[3];
    const float* c1b = (const float*)d_in[4];
    const float* c2W = (const float*)d_in[5];
    const float* c2r = (const float*)d_in[6];
    const float* c2b = (const float*)d_in[7];
    const float* dw1 = (const float*)d_in[8];
    const float* db1 = (const float*)d_in[9];
    const float* dw2 = (const float*)d_in[10];
    const float* db2 = (const float*)d_in[11];
    float* out = (float*)d_out;

    void *pB2c;
    void *pA1h, *pA1l, *pWh, *pWl, *pZh, *pZl;
    void *pB1h, *pB1l, *pB2h, *pB2l, *pD1h, *pD1l, *pD2h, *pD2l;
    cudaGetSymbolAddress(&pB2c, g_b2c);
    cudaGetSymbolAddress(&pA1h, g_A1h); cudaGetSymbolAddress(&pA1l, g_A1l);
    cudaGetSymbolAddress(&pWh, g_wh);   cudaGetSymbolAddress(&pWl, g_wl);
    cudaGetSymbolAddress(&pZh, g_zh);   cudaGetSymbolAddress(&pZl, g_zl);
    cudaGetSymbolAddress(&pB1h, g_B1h); cudaGetSymbolAddress(&pB1l, g_B1l);
    cudaGetSymbolAddress(&pB2h, g_B2h); cudaGetSymbolAddress(&pB2l, g_B2l);
    cudaGetSymbolAddress(&pD1h, g_D1h); cudaGetSymbolAddress(&pD1l, g_D1l);
    cudaGetSymbolAddress(&pD2h, g_D2h); cudaGetSymbolAddress(&pD2l, g_D2l);

    // smem: h planes 67584 + A stage 10240 + B stage 2*KC*(N1+8)*2 = 33792
    const int SM_F = 67584 + 10240 + 33792;  // 111616 -> occ 2
    cudaFuncSetAttribute(fused2_k<128, 256, 256, 128, true>,
                         cudaFuncAttributeMaxDynamicSharedMemorySize, SM_F);
    cudaFuncSetAttribute(fused2_k<64, 256, 256, 64, false>,
                         cudaFuncAttributeMaxDynamicSharedMemorySize, SM_F);

    const int nFG = (NNODES + 63) / 64;                 // 782
    const int nEdgeBlocks = (NEDGES + 255) / 256;
    const int nAggBlocks  = (NNODES * 32 + 255) / 256;
    const int nNodeBlocks = (NNODES + 255) / 256;

    // --- CSR build (g_cnt is zero at entry; scan3 re-zeroes it) ---
    hist_k<<<nEdgeBlocks, 256>>>(ei);
    scan1_k<<<NB_SCAN, 1024>>>();
    scan3_k<<<nNodeBlocks, 256>>>();
    place_k<<<nEdgeBlocks, 256>>>(ei);

    // --- conv1 input aggregation (ncu capture slot #5) ---
    agg1_k<<<nAggBlocks, 256>>>(x);
    prep_k<<<128, 256>>>(c1W, c1r, c2W, c2r, c2b, dw1, dw2);

    // --- fused conv1 GEMM + conv2 weight GEMM: A1 -> h(smem) -> hWr ---
    fused2_k<128, 256, 256, 128, true><<<nFG, 256, SM_F>>>(
        (const __nv_bfloat16*)pA1h, (const __nv_bfloat16*)pA1l,
        (const __nv_bfloat16*)pB1h, (const __nv_bfloat16*)pB1l, c1b,
        (const __nv_bfloat16*)pB2h, (const __nv_bfloat16*)pB2l, (const float*)pB2c,
        nullptr, (__nv_bfloat16*)pWh, (__nv_bfloat16*)pWl, NNODES);

    // --- conv2 aggregation -> z ---
    agg2_k<<<nAggBlocks, 256>>>();

    // --- fused decoder: z -> h2(smem) -> out ---
    fused2_k<64, 256, 256, 64, false><<<nFG, 256, SM_F>>>(
        (const __nv_bfloat16*)pZh, (const __nv_bfloat16*)pZl,
        (const __nv_bfloat16*)pD1h, (const __nv_bfloat16*)pD1l, db1,
        (const __nv_bfloat16*)pD2h, (const __nv_bfloat16*)pD2l, db2,
        out, nullptr, nullptr, NNODES);
}